// round 2
// baseline (speedup 1.0000x reference)
#include <cuda_runtime.h>
#include <cstdint>

#define BB 2
#define SQ 1024
#define SK 1024
#define DD 64
#define DV 64
#define NSPLIT 16
#define KCHUNK (SK / NSPLIT)   // 64
#define QPB 64                 // queries per block
#define TPB 128                // threads per block (2 per query)

#define LOG2E 1.4426950408889634f

typedef unsigned long long ull;

// partial accumulators, d-pair-major: [b][split][dpair(32)][q(1024)] of ull (2 floats)
__device__ ull   g_pacc[(size_t)BB * NSPLIT * (DV / 2) * SQ];
// partial softmax denominators: [b][split][q]
__device__ float g_pl[(size_t)BB * NSPLIT * SQ];

__device__ __forceinline__ ull add_f32x2(ull a, ull b) {
    ull r;
    asm("add.rn.f32x2 %0, %1, %2;" : "=l"(r) : "l"(a), "l"(b));
    return r;
}
__device__ __forceinline__ ull fma_f32x2(ull a, ull b, ull c) {
    ull r;
    asm("fma.rn.f32x2 %0, %1, %2, %3;" : "=l"(r) : "l"(a), "l"(b), "l"(c));
    return r;
}
__device__ __forceinline__ ull pack_dup(float p) {
    ull r;
    asm("mov.b64 %0, {%1, %1};" : "=l"(r) : "r"(__float_as_uint(p)));
    return r;
}
__device__ __forceinline__ float ex2(float x) {
    float r;
    asm("ex2.approx.f32 %0, %1;" : "=f"(r) : "f"(x));
    return r;
}

#define ABS2_MASK 0x7FFFFFFF7FFFFFFFULL

// L1 distance over this thread's 32-dim half: 8x LDS.128, 16 diff-add2,
// 32 LOP3 (abs), 15-add2 tree, 1 scalar add.
__device__ __forceinline__ float half_l1(const ulonglong2* __restrict__ kp,
                                         const ull* __restrict__ qn)
{
    ull t[16];
#pragma unroll
    for (int i = 0; i < 8; i++) {
        ulonglong2 kk = kp[i];
        t[2 * i]     = add_f32x2(kk.x, qn[2 * i])     & ABS2_MASK;
        t[2 * i + 1] = add_f32x2(kk.y, qn[2 * i + 1]) & ABS2_MASK;
    }
#pragma unroll
    for (int i = 0; i < 8; i++) t[i] = add_f32x2(t[i], t[i + 8]);
#pragma unroll
    for (int i = 0; i < 4; i++) t[i] = add_f32x2(t[i], t[i + 4]);
    t[0] = add_f32x2(t[0], t[2]);
    t[1] = add_f32x2(t[1], t[3]);
    t[0] = add_f32x2(t[0], t[1]);
    float2 f = *(float2*)&t[0];
    return f.x + f.y;
}

__global__ __launch_bounds__(TPB)
void attn_partial(const float* __restrict__ q, const float* __restrict__ k,
                  const float* __restrict__ v, const int* __restrict__ mask)
{
    const int b     = blockIdx.z;
    const int s     = blockIdx.y;
    const int tid   = threadIdx.x;
    const int h     = tid & 1;        // which 32-dim half
    const int qloc  = tid >> 1;
    const int qi    = blockIdx.x * QPB + qloc;

    __shared__ __align__(16) float ks[KCHUNK][DD];
    __shared__ __align__(16) float vs[KCHUNK][DV];
    __shared__ __align__(16) float k0s[DD];
    __shared__ float bias[KCHUNK];

    const float* kbase = k + ((size_t)b * SK + (size_t)s * KCHUNK) * DD;
    const float* vbase = v + ((size_t)b * SK + (size_t)s * KCHUNK) * DV;
#pragma unroll
    for (int i = tid; i < KCHUNK * DD / 4; i += TPB) {
        ((float4*)&ks[0][0])[i] = ((const float4*)kbase)[i];
        ((float4*)&vs[0][0])[i] = ((const float4*)vbase)[i];
    }
    if (tid < KCHUNK)
        bias[tid] = mask[(size_t)b * SK + (size_t)s * KCHUNK + tid] ? 0.0f : 1e9f;
    if (tid < DD / 4)
        ((float4*)k0s)[tid] = ((const float4*)(k + (size_t)b * SK * DD))[tid];

    // this thread's negated q half, packed f32x2
    ull qn[16];
    const float* qrow = q + ((size_t)b * SQ + qi) * DD + h * 32;
#pragma unroll
    for (int i = 0; i < 8; i++) {
        float4 t = ((const float4*)qrow)[i];
        float2 a = make_float2(-t.x, -t.y);
        float2 c = make_float2(-t.z, -t.w);
        qn[2 * i]     = *(ull*)&a;
        qn[2 * i + 1] = *(ull*)&c;
    }
    __syncthreads();

    // shared reference point: dist0 = L1(q, k[b][0]) (same across all splits)
    float dh0 = half_l1((const ulonglong2*)(k0s + h * 32), qn);
    float dist0 = dh0 + __shfl_xor_sync(0xffffffffu, dh0, 1);
    float d0l2 = dist0 * LOG2E;

    ull acc[16];
#pragma unroll
    for (int i = 0; i < 16; i++) acc[i] = 0ULL;
    float lsum = 0.0f;

#pragma unroll 2
    for (int j = 0; j < KCHUNK; j++) {
        float dh = half_l1((const ulonglong2*)(&ks[j][h * 32]), qn);
        float dist = dh + __shfl_xor_sync(0xffffffffu, dh, 1);
        float db = dist + bias[j];                 // +1e9 if masked -> p flushes to 0
        float p = ex2(fmaf(db, -LOG2E, d0l2));     // exp(dist0 - dist - bias)
        lsum += p;
        ull pp = pack_dup(p);

        const ulonglong2* vp = (const ulonglong2*)(&vs[j][h * 32]);
#pragma unroll
        for (int i = 0; i < 8; i++) {
            ulonglong2 vv = vp[i];
            acc[2 * i]     = fma_f32x2(vv.x, pp, acc[2 * i]);
            acc[2 * i + 1] = fma_f32x2(vv.y, pp, acc[2 * i + 1]);
        }
    }

    // store partials d-pair-major: [b][s][dp][q], fully coalesced STG.64
    ull* pb = g_pacc + ((size_t)(b * NSPLIT + s) * (DV / 2)) * SQ;
#pragma unroll
    for (int i = 0; i < 16; i++) {
        int dp = h * 16 + i;
        pb[(size_t)dp * SQ + qi] = acc[i];
    }
    if (h == 0)
        g_pl[(size_t)(b * NSPLIT + s) * SQ + qi] = lsum;
}

// combine: grid (SQ/32, DV/2/8, BB), block 256 = 32 queries x 8 dpairs
__global__ __launch_bounds__(256)
void attn_combine(float* __restrict__ out)
{
    const int tid = threadIdx.x;
    const int qq  = tid & 31;
    const int dpl = tid >> 5;                    // 0..7
    const int dp  = blockIdx.y * 8 + dpl;        // 0..31
    const int qi  = blockIdx.x * 32 + qq;
    const int b   = blockIdx.z;

    __shared__ float linv[32];

    // denominators for this block's 32 queries (first warp)
    if (tid < 32) {
        float lt = 0.0f;
#pragma unroll
        for (int s = 0; s < NSPLIT; s++)
            lt += g_pl[(size_t)(b * NSPLIT + s) * SQ + blockIdx.x * 32 + tid];
        linv[tid] = 1.0f / lt;
    }

    // accumulate this (qi, dp) over splits — 16 independent coalesced LDG.64
    float sx = 0.0f, sy = 0.0f;
#pragma unroll
    for (int s = 0; s < NSPLIT; s++) {
        ull t = g_pacc[((size_t)(b * NSPLIT + s) * (DV / 2) + dp) * SQ + qi];
        float2 f = *(float2*)&t;
        sx += f.x;
        sy += f.y;
    }
    __syncthreads();
    float li = linv[qq];
    float2 r = make_float2(sx * li, sy * li);
    *(float2*)&out[((size_t)b * SQ + qi) * DV + 2 * dp] = r;
}

extern "C" void kernel_launch(void* const* d_in, const int* in_sizes, int n_in,
                              void* d_out, int out_size)
{
    const float* q    = (const float*)d_in[0];
    const float* k    = (const float*)d_in[1];
    const float* v    = (const float*)d_in[2];
    const int*   mask = (const int*)d_in[3];
    float* out = (float*)d_out;

    dim3 gridP(SQ / QPB, NSPLIT, BB);
    attn_partial<<<gridP, TPB>>>(q, k, v, mask);

    dim3 gridC(SQ / 32, (DV / 2) / 8, BB);
    attn_combine<<<gridC, 256>>>(out);
}